// round 17
// baseline (speedup 1.0000x reference)
#include <cuda_runtime.h>
#include <cstdint>
#include <cstddef>

// Fixed shapes: B=1, N=1000, T=256, D=512, M=258, NUM=10
// out row = 3082 floats (12328 B; 16B-aligned only for even n)
#define N_CAND   1000
#define T_DIM    256
#define D_DIM    512
#define M_DIM    258
#define NUMF     10
#define ROW_OUT  3082
#define R4       (D_DIM / 4)       // 128 float4 per section
#define R8       (D_DIM / 8)       // 64  v8-lanes per section

// Blackwell 256-bit global load (sm_100+): one LDG.E.256 = 32 bytes.
// Halves L1tex wavefront count vs 2x LDG.128 for the same bytes.
struct v8 { float4 lo, hi; };

__device__ __forceinline__ v8 ldg_256(const float* p) {
    v8 r;
    asm volatile(
        "ld.global.nc.v8.f32 {%0,%1,%2,%3,%4,%5,%6,%7}, [%8];"
        : "=f"(r.lo.x), "=f"(r.lo.y), "=f"(r.lo.z), "=f"(r.lo.w),
          "=f"(r.hi.x), "=f"(r.hi.y), "=f"(r.hi.z), "=f"(r.hi.w)
        : "l"(p));
    return r;
}

// One block per candidate, 128 threads. The 6 sections form 384 v8-lanes;
// thread t owns lanes {t, t+128, t+256} -> 3 independent LDG.256.
__global__ __launch_bounds__(128) void feature_gather_v8(
    const int* __restrict__ cand,        // [N,6]
    const float* __restrict__ num,       // [N,10]
    const float* __restrict__ blo,       // [N,T,D]
    const float* __restrict__ att,       // [N,M,D]
    float* __restrict__ out)             // [N,3082]
{
    const int n = blockIdx.x;
    const int t = threadIdx.x;

    const int2* cp = (const int2*)(cand + n * 6);
    const int2 p01 = __ldg(cp + 0);      // c0, c1
    const int2 p23 = __ldg(cp + 1);      // c2, c3
    const int2 p45 = __ldg(cp + 2);      // c4, c5

    const float* bbase = blo + (size_t)n * T_DIM * D_DIM;
    const float* abase = att + (size_t)n * M_DIM * D_DIM;

    // Section source rows, in output order.
    const float* src[6] = {
        bbase + (size_t)p01.y * D_DIM,          // 0: blo[c1]
        bbase + (size_t)p23.x * D_DIM,          // 1: blo[c2]
        bbase + (size_t)p45.x * D_DIM,          // 2: blo[c4]
        bbase + (size_t)p45.y * D_DIM,          // 3: blo[c5]
        abase + (size_t)(p01.x + 2) * D_DIM,    // 4: att[c0+2]
        abase + (size_t)(p23.y + 2) * D_DIM };  // 5: att[c3+2]

    // Three v8 lanes per thread: l0 = t (sections 0/1), l1 = t+128 (2/3),
    // l2 = t+256 (4/5). lane -> (section = lane>>6, idx = lane&63).
    const int l0 = t, l1 = t + 128, l2 = t + 256;
    const int s0 = l0 >> 6, i0 = l0 & 63;
    const int s1 = l1 >> 6, i1 = l1 & 63;
    const int s2 = l2 >> 6, i2 = l2 & 63;

    // Front-batched 256-bit loads (3 per thread, 96 B in flight).
    const v8 a = ldg_256(src[s0] + i0 * 8);
    const v8 b = ldg_256(src[s1] + i1 * 8);
    const v8 c = ldg_256(src[s2] + i2 * 8);

    float* outRow = out + (size_t)n * ROW_OUT;

    if ((n & 1) == 0) {
        // 16B-aligned row: each v8 lane = two consecutive float4 slots.
        float4* o4 = (float4*)outRow;
        float4* d0 = o4 + s0 * R4 + i0 * 2;
        float4* d1 = o4 + s1 * R4 + i1 * 2;
        float4* d2 = o4 + s2 * R4 + i2 * 2;
        d0[0] = a.lo; d0[1] = a.hi;
        d1[0] = b.lo; d1[1] = b.hi;
        d2[0] = c.lo; d2[1] = c.hi;
    } else {
        // 8B-aligned row: four float2 per v8 lane.
        float2* o2 = (float2*)outRow;
        #define STL(s, i, v)                                             \
            {   float2* d = o2 + ((s) * R4 + (i) * 2) * 2;               \
                d[0] = make_float2((v).lo.x, (v).lo.y);                  \
                d[1] = make_float2((v).lo.z, (v).lo.w);                  \
                d[2] = make_float2((v).hi.x, (v).hi.y);                  \
                d[3] = make_float2((v).hi.z, (v).hi.w); }
        STL(s0, i0, a) STL(s1, i1, b) STL(s2, i2, c)
        #undef STL
    }

    // Numeric features: 10 floats = 5 float2, threads 0..4.
    if (t < NUMF / 2) {
        const float2* num2 = (const float2*)(num + (size_t)n * NUMF);
        ((float2*)outRow)[6 * (D_DIM / 2) + t] = __ldg(num2 + t);
    }
}

extern "C" void kernel_launch(void* const* d_in, const int* in_sizes, int n_in,
                              void* d_out, int out_size) {
    const int*   cand = (const int*)d_in[0];
    const float* num  = (const float*)d_in[1];
    const float* blo  = (const float*)d_in[2];
    const float* att  = (const float*)d_in[3];
    float* out = (float*)d_out;

    feature_gather_v8<<<N_CAND, 128>>>(cand, num, blo, att, out);
}